// round 14
// baseline (speedup 1.0000x reference)
#include <cuda_runtime.h>
#include <cuda_fp16.h>
#include <cstdint>
#include <math.h>

static constexpr int BB = 65536;
static constexpr int DD = 64;
static constexpr int HH = 512;

// ---------------- scratch (__device__ globals; allocation-free rule) -------------
__device__ __align__(16) __half g_x [(size_t)BB * DD];
__device__ __align__(16) __half g_h0[(size_t)BB * HH];
__device__ __align__(16) __half g_h1[(size_t)BB * HH];
__device__ __align__(16) __half g_da[(size_t)BB * HH];   // d2, then reused for d0
__device__ __align__(16) __half g_d1[(size_t)BB * HH];
// Weights. Forward needs W^T ([N,K] K-major); backward needs W direct ([N,K]).
__device__ __align__(16) __half g_W0T[HH * DD];          // [512,64]
__device__ __align__(16) __half g_W1T[HH * HH];
__device__ __align__(16) __half g_W2T[HH * HH];
__device__ __align__(16) __half g_W1 [HH * HH];
__device__ __align__(16) __half g_W2 [HH * HH];
__device__ __align__(16) __half g_W0 [DD * HH];          // [64,512]

// ---------------- helpers (all base-target PTX: sm_80-era) ----------------
__device__ __forceinline__ uint32_t smem_u32(const void* p) {
    uint32_t a;
    asm("{ .reg .u64 t; cvta.to.shared.u64 t, %1; cvt.u32.u64 %0, t; }" : "=r"(a) : "l"(p));
    return a;
}
__device__ __forceinline__ void cp16(uint32_t s, const void* g) {
    asm volatile("cp.async.cg.shared.global [%0], [%1], 16;" :: "r"(s), "l"(g));
}
#define CP_COMMIT() asm volatile("cp.async.commit_group;" ::: "memory")
#define CP_WAIT2()  asm volatile("cp.async.wait_group 2;" ::: "memory")

#define LDSM4(R, addr)                                                                   \
    asm volatile("ldmatrix.sync.aligned.m8n8.x4.shared.b16 {%0,%1,%2,%3}, [%4];"         \
        : "=r"((R)[0]), "=r"((R)[1]), "=r"((R)[2]), "=r"((R)[3]) : "r"(addr))

#define MMAH(C, A, b0_, b1_)                                                             \
    asm volatile("mma.sync.aligned.m16n8k16.row.col.f32.f16.f16.f32 "                    \
        "{%0,%1,%2,%3},{%4,%5,%6,%7},{%8,%9},{%0,%1,%2,%3};"                             \
        : "+f"((C)[0]), "+f"((C)[1]), "+f"((C)[2]), "+f"((C)[3])                         \
        : "r"((A)[0]), "r"((A)[1]), "r"((A)[2]), "r"((A)[3]), "r"(b0_), "r"(b1_))

__device__ __forceinline__ float tanh_fast(float x) {
    float e = __expf(2.0f * x);
    return 1.0f - __fdividef(2.0f, e + 1.0f);
}
__device__ __forceinline__ float sech2_of(float z) {   // 1 - tanh(z)^2
    float e = __expf(2.0f * z);
    float s = __fdividef(2.0f, e + 1.0f);              // s = 1 - tanh
    return s * (2.0f - s);
}
__device__ __forceinline__ uint32_t pack_h2(float a, float b) {
    __half2 h = __floats2half2_rn(a, b);
    return *reinterpret_cast<uint32_t*>(&h);
}
__device__ __forceinline__ float h2lo(uint32_t u) {
    return __half2float(__ushort_as_half((unsigned short)(u & 0xFFFF)));
}
__device__ __forceinline__ float h2hi(uint32_t u) {
    return __half2float(__ushort_as_half((unsigned short)(u >> 16)));
}

// ---------------- prep kernels: fp32 -> fp16 ----------------
__global__ void half_direct(const float* __restrict__ src, __half* __restrict__ dst, int n) {
    int i = blockIdx.x * blockDim.x + threadIdx.x;
    if (i < n) dst[i] = __float2half_rn(src[i]);
}
__global__ void half_trans(const float* __restrict__ src, __half* __restrict__ dst,
                           int R, int C) {
    int i = blockIdx.x * blockDim.x + threadIdx.x;
    if (i < R * C) {
        int r = i / C, c = i % C;
        dst[(size_t)c * R + r] = __float2half_rn(src[i]);
    }
}

// ---------------- HMMA stage loader (padded 80B rows, conflict-free ldmatrix) -----
template<int BN>
__device__ __forceinline__ void load_stage(
    uint32_t base_u, int buf,
    const __half* __restrict__ A, const __half* __restrict__ B,
    int bm, int bn, int K, int k0, int tid)
{
    constexpr int ASZ = 128 * 80;
    constexpr int BSZ = BN * 80;
    constexpr int STAGE = ASZ + BSZ;
    uint32_t sb = base_u + (uint32_t)(buf * STAGE);
#pragma unroll
    for (int i = tid; i < 128 * 4; i += 256) {
        int r = i >> 2, cc = i & 3;
        cp16(sb + (uint32_t)(r * 80 + cc * 16), A + (size_t)(bm + r) * K + k0 + cc * 8);
    }
#pragma unroll
    for (int i = tid; i < BN * 4; i += 256) {
        int r = i >> 2, cc = i & 3;
        cp16(sb + (uint32_t)(ASZ + r * 80 + cc * 16), B + (size_t)(bn + r) * K + k0 + cc * 8);
    }
}

// ---------------- FFMA tile path (R0-style fp32 SGEMM on fp16 inputs) -------------
// Runs on the fma pipe; coexists with HMMA CTAs on the same SM.
template<int MODE>
__device__ void ffma_tile(char* sm,
                          const __half* __restrict__ A, const __half* __restrict__ B,
                          const float* __restrict__ bias, const float* __restrict__ w3,
                          const __half* __restrict__ G, __half* __restrict__ O,
                          int K, int bm, int bn, int tid)
{
    float* As = reinterpret_cast<float*>(sm);          // [8][128]
    float* Bs = As + 8 * 128;                          // [8][128]
    const int tcol = tid & 15;                         // 16 cols of 8
    const int trow = tid >> 4;                         // 16 rows of 8

    float acc[8][8];
#pragma unroll
    for (int i = 0; i < 8; i++)
#pragma unroll
        for (int j = 0; j < 8; j++) acc[i][j] = 0.f;

    const int m0 = tid >> 1, k40 = (tid & 1) << 2;     // loader coords (4 halves each)

    for (int k0 = 0; k0 < K; k0 += 8) {
        {   // A tile: As[kk][m] ; B tile: Bs[kk][n]  (both operands are [rows, K])
            uint2 ua = *reinterpret_cast<const uint2*>(A + (size_t)(bm + m0) * K + k0 + k40);
            const __half2* ha = reinterpret_cast<const __half2*>(&ua);
            float2 fa0 = __half22float2(ha[0]), fa1 = __half22float2(ha[1]);
            As[(k40 + 0) * 128 + m0] = fa0.x;
            As[(k40 + 1) * 128 + m0] = fa0.y;
            As[(k40 + 2) * 128 + m0] = fa1.x;
            As[(k40 + 3) * 128 + m0] = fa1.y;
            uint2 ub = *reinterpret_cast<const uint2*>(B + (size_t)(bn + m0) * K + k0 + k40);
            const __half2* hb = reinterpret_cast<const __half2*>(&ub);
            float2 fb0 = __half22float2(hb[0]), fb1 = __half22float2(hb[1]);
            Bs[(k40 + 0) * 128 + m0] = fb0.x;
            Bs[(k40 + 1) * 128 + m0] = fb0.y;
            Bs[(k40 + 2) * 128 + m0] = fb1.x;
            Bs[(k40 + 3) * 128 + m0] = fb1.y;
        }
        __syncthreads();
#pragma unroll
        for (int kk = 0; kk < 8; kk++) {
            float ra[8], rb[8];
#pragma unroll
            for (int i = 0; i < 8; i++) ra[i] = As[kk * 128 + trow * 8 + i];
#pragma unroll
            for (int j = 0; j < 8; j++) rb[j] = Bs[kk * 128 + tcol * 8 + j];
#pragma unroll
            for (int i = 0; i < 8; i++)
#pragma unroll
                for (int j = 0; j < 8; j++)
                    acc[i][j] = fmaf(ra[i], rb[j], acc[i][j]);
        }
        __syncthreads();
    }

    // fused epilogue (fp16 outputs, pairs)
#pragma unroll
    for (int i = 0; i < 8; i++) {
        const int m = bm + trow * 8 + i;
#pragma unroll
        for (int j = 0; j < 8; j += 2) {
            const int gn = bn + tcol * 8 + j;
            float c0 = acc[i][j], c1 = acc[i][j + 1];
            float v0, v1;
            if (MODE == 0) {
                v0 = tanh_fast(c0 + bias[gn]);
                v1 = tanh_fast(c1 + bias[gn + 1]);
            } else if (MODE == 1) {
                v0 = w3[gn]     * sech2_of(c0 + bias[gn]);
                v1 = w3[gn + 1] * sech2_of(c1 + bias[gn + 1]);
            } else { // MODE 2
                uint32_t gw = *reinterpret_cast<const uint32_t*>(G + (size_t)m * HH + gn);
                float ga = h2lo(gw), gb = h2hi(gw);
                v0 = c0 * (1.0f - ga * ga);
                v1 = c1 * (1.0f - gb * gb);
            }
            *reinterpret_cast<uint32_t*>(O + (size_t)m * HH + gn) = pack_h2(v0, v1);
        }
    }
}

// ---------------- hybrid kernel: HMMA tiles + FFMA tiles in one launch ------------
// MODE 0: h = tanh(v + bias[n]); MODE 1: w3*(1-tanh^2); MODE 2: v*(1-g^2);
// MODE 3: symplectic fp32 (pure HMMA, BN=64).
template<int MODE, int BN, int WARPS_M>
__global__ void __launch_bounds__(256, 2)
hnn_mma(const __half* __restrict__ A, const __half* __restrict__ B,
        const float* __restrict__ bias, const float* __restrict__ w3,
        const __half* __restrict__ G, __half* __restrict__ O,
        float* __restrict__ Of, int K)
{
    constexpr int WARPS_N = 8 / WARPS_M;
    constexpr int WM = 128 / WARPS_M;
    constexpr int WN = BN / WARPS_N;
    constexpr int MI = WM / 16;
    constexpr int NI = WN / 8;
    constexpr int ASZ = 128 * 80;
    constexpr int BSZ = BN * 80;
    constexpr int STAGE = ASZ + BSZ;

    extern __shared__ char sm[];
    const int tid = threadIdx.x;
    const int bm = blockIdx.y * 128;
    const int bn = blockIdx.x * BN;

    // 3/8 of tiles take the FFMA (fma-pipe) path; rest take HMMA (tensor pipe).
    if (BN == 128 && MODE != 3) {
        if (((blockIdx.y * 4 + blockIdx.x) & 7) < 3) {
            ffma_tile<MODE>(sm, A, B, bias, w3, G, O, K, bm, bn, tid);
            return;
        }
    }

    const uint32_t base_u = smem_u32(sm);
    const int lane = tid & 31;
    const int wid = tid >> 5;
    const int wm = wid % WARPS_M;
    const int wn = wid / WARPS_M;
    const int NK = K >> 5;

    float acc[MI][NI][4];
#pragma unroll
    for (int mi = 0; mi < MI; mi++)
#pragma unroll
        for (int ni = 0; ni < NI; ni++)
#pragma unroll
            for (int r = 0; r < 4; r++) acc[mi][ni][r] = 0.0f;

    load_stage<BN>(base_u, 0, A, B, bm, bn, K, 0, tid);
    CP_COMMIT();
    if (NK > 1) load_stage<BN>(base_u, 1, A, B, bm, bn, K, 32, tid);
    CP_COMMIT();

    for (int ks = 0; ks < NK; ks++) {
        if (ks + 2 < NK)
            load_stage<BN>(base_u, (ks + 2) & 3, A, B, bm, bn, K, (ks + 2) << 5, tid);
        CP_COMMIT();
        CP_WAIT2();
        __syncthreads();

        const uint32_t sb = base_u + (uint32_t)((ks & 3) * STAGE);
#pragma unroll
        for (int kk = 0; kk < 2; kk++) {
            const int kb = kk * 16;
            uint32_t af[MI][4];
#pragma unroll
            for (int mi = 0; mi < MI; mi++) {
                uint32_t addr = sb + (uint32_t)((wm * WM + mi * 16 + (lane & 15)) * 80 +
                                                (kb + (lane >> 4) * 8) * 2);
                LDSM4(af[mi], addr);
            }
#pragma unroll
            for (int n2 = 0; n2 < NI / 2; n2++) {
                uint32_t baddr = sb + (uint32_t)(ASZ +
                    (wn * WN + n2 * 16 + ((lane >> 4) << 3) + (lane & 7)) * 80 +
                    (kb + ((lane >> 3) & 1) * 8) * 2);
                uint32_t bf[4];
                LDSM4(bf, baddr);
#pragma unroll
                for (int mi = 0; mi < MI; mi++) {
                    MMAH(acc[mi][2 * n2],     af[mi], bf[0], bf[1]);
                    MMAH(acc[mi][2 * n2 + 1], af[mi], bf[2], bf[3]);
                }
            }
        }
    }

    // -------- fused epilogue (HMMA path) --------
#pragma unroll
    for (int mi = 0; mi < MI; mi++) {
#pragma unroll
        for (int ni = 0; ni < NI; ni++) {
            float c0 = acc[mi][ni][0], c1 = acc[mi][ni][1];
            float c2 = acc[mi][ni][2], c3 = acc[mi][ni][3];
            const int gn = bn + wn * WN + ni * 8 + (lane & 3) * 2;
            const int r0 = bm + wm * WM + mi * 16 + (lane >> 2);
            const int r1 = r0 + 8;

            if (MODE == 0 || MODE == 1) {
                const float bb0 = bias[gn], bb1 = bias[gn + 1];
                float v0, v1, v2, v3;
                if (MODE == 0) {
                    v0 = tanh_fast(c0 + bb0); v1 = tanh_fast(c1 + bb1);
                    v2 = tanh_fast(c2 + bb0); v3 = tanh_fast(c3 + bb1);
                } else {
                    const float w0 = w3[gn], w1 = w3[gn + 1];
                    v0 = w0 * sech2_of(c0 + bb0); v1 = w1 * sech2_of(c1 + bb1);
                    v2 = w0 * sech2_of(c2 + bb0); v3 = w1 * sech2_of(c3 + bb1);
                }
                *reinterpret_cast<uint32_t*>(O + (size_t)r0 * HH + gn) = pack_h2(v0, v1);
                *reinterpret_cast<uint32_t*>(O + (size_t)r1 * HH + gn) = pack_h2(v2, v3);
            } else if (MODE == 2) {
                uint32_t gw0 = *reinterpret_cast<const uint32_t*>(G + (size_t)r0 * HH + gn);
                uint32_t gw1 = *reinterpret_cast<const uint32_t*>(G + (size_t)r1 * HH + gn);
                float ga = h2lo(gw0), gb = h2hi(gw0);
                float gc = h2lo(gw1), gd = h2hi(gw1);
                float v0 = c0 * (1.0f - ga * ga), v1 = c1 * (1.0f - gb * gb);
                float v2 = c2 * (1.0f - gc * gc), v3 = c3 * (1.0f - gd * gd);
                *reinterpret_cast<uint32_t*>(O + (size_t)r0 * HH + gn) = pack_h2(v0, v1);
                *reinterpret_cast<uint32_t*>(O + (size_t)r1 * HH + gn) = pack_h2(v2, v3);
            } else { // MODE 3: out[:,0:32] = grad[:,32:64]; out[:,32:64] = -grad[:,0:32]
                const int dc = (gn >= 32) ? gn - 32 : gn + 32;
                const float sgn = (gn >= 32) ? 1.0f : -1.0f;
                float2 t0; t0.x = sgn * c0; t0.y = sgn * c1;
                float2 t1; t1.x = sgn * c2; t1.y = sgn * c3;
                *reinterpret_cast<float2*>(Of + (size_t)r0 * DD + dc) = t0;
                *reinterpret_cast<float2*>(Of + (size_t)r1 * DD + dc) = t1;
            }
        }
    }
}

// ---------------- host ----------------
extern "C" void kernel_launch(void* const* d_in, const int* in_sizes, int n_in,
                              void* d_out, int out_size)
{
    const float* x  = (const float*)d_in[1];
    const float* W0 = (const float*)d_in[2];
    const float* b0 = (const float*)d_in[3];
    const float* W1 = (const float*)d_in[4];
    const float* b1 = (const float*)d_in[5];
    const float* W2 = (const float*)d_in[6];
    const float* b2 = (const float*)d_in[7];
    const float* W3 = (const float*)d_in[8];
    float* out = (float*)d_out;

    __half *xq, *h0, *h1, *da, *d1;
    __half *W0T, *W1T, *W2T, *W1q, *W2q, *W0q;
    cudaGetSymbolAddress((void**)&xq,  g_x);
    cudaGetSymbolAddress((void**)&h0,  g_h0);
    cudaGetSymbolAddress((void**)&h1,  g_h1);
    cudaGetSymbolAddress((void**)&da,  g_da);
    cudaGetSymbolAddress((void**)&d1,  g_d1);
    cudaGetSymbolAddress((void**)&W0T, g_W0T);
    cudaGetSymbolAddress((void**)&W1T, g_W1T);
    cudaGetSymbolAddress((void**)&W2T, g_W2T);
    cudaGetSymbolAddress((void**)&W1q, g_W1);
    cudaGetSymbolAddress((void**)&W2q, g_W2);
    cudaGetSymbolAddress((void**)&W0q, g_W0);

    // HMMA path: 4 buffers of (A 128*80 + B BN*80). FFMA path uses first 8KB as fp32 tiles.
    constexpr int SM128 = 4 * (128 * 80 + 128 * 80);   // 81920 -> 2 CTAs/SM
    constexpr int SM64  = 4 * (128 * 80 + 64 * 80);    // 61440
    cudaFuncSetAttribute(hnn_mma<0, 128, 4>, cudaFuncAttributeMaxDynamicSharedMemorySize, SM128);
    cudaFuncSetAttribute(hnn_mma<1, 128, 4>, cudaFuncAttributeMaxDynamicSharedMemorySize, SM128);
    cudaFuncSetAttribute(hnn_mma<2, 128, 4>, cudaFuncAttributeMaxDynamicSharedMemorySize, SM128);
    cudaFuncSetAttribute(hnn_mma<3, 64, 8>,  cudaFuncAttributeMaxDynamicSharedMemorySize, SM64);

    // ---- prep: convert/transpose operands into fp16 ----
    {
        int n;
        n = BB * DD; half_direct<<<(n + 255) / 256, 256>>>(x, xq, n);
        n = DD * HH; half_direct<<<(n + 255) / 256, 256>>>(W0, W0q, n);
        half_trans<<<(n + 255) / 256, 256>>>(W0, W0T, DD, HH);
        n = HH * HH;
        half_direct<<<(n + 255) / 256, 256>>>(W1, W1q, n);
        half_direct<<<(n + 255) / 256, 256>>>(W2, W2q, n);
        half_trans<<<(n + 255) / 256, 256>>>(W1, W1T, HH, HH);
        half_trans<<<(n + 255) / 256, 256>>>(W2, W2T, HH, HH);
    }

    const dim3 gH(HH / 128, BB / 128);   // (4, 512)
    const dim3 gO(1,        BB / 128);   // (1, 512)

    // 1) h0 = tanh(x @ W0 + b0)
    hnn_mma<0, 128, 4><<<gH, 256, SM128>>>(xq, W0T, b0, nullptr, nullptr, h0, nullptr, DD);
    // 2) h1 = tanh(h0 @ W1 + b1)
    hnn_mma<0, 128, 4><<<gH, 256, SM128>>>(h0, W1T, b1, nullptr, nullptr, h1, nullptr, HH);
    // 3) d2 = W3 * (1 - tanh^2(h1 @ W2 + b2))
    hnn_mma<1, 128, 4><<<gH, 256, SM128>>>(h1, W2T, b2, W3, nullptr, da, nullptr, HH);
    // 4) d1 = (d2 @ W2^T) * (1 - h1^2)
    hnn_mma<2, 128, 4><<<gH, 256, SM128>>>(da, W2q, nullptr, nullptr, h1, d1, nullptr, HH);
    // 5) d0 = (d1 @ W1^T) * (1 - h0^2)   (reuse da buffer)
    hnn_mma<2, 128, 4><<<gH, 256, SM128>>>(d1, W1q, nullptr, nullptr, h0, da, nullptr, HH);
    // 6) out = symplectic(d0 @ W0^T)
    hnn_mma<3, 64, 8><<<gO, 256, SM64>>>(da, W0q, nullptr, nullptr, nullptr, nullptr, out, HH);
}

// round 15
// speedup vs baseline: 4.4965x; 4.4965x over previous
#include <cuda_runtime.h>
#include <cuda_fp16.h>
#include <cstdint>
#include <math.h>

static constexpr int BB = 65536;
static constexpr int DD = 64;
static constexpr int HH = 512;

// ---------------- scratch (__device__ globals; allocation-free rule) -------------
__device__ __align__(16) __half g_x [(size_t)BB * DD];
__device__ __align__(16) __half g_h0[(size_t)BB * HH];
__device__ __align__(16) __half g_h1[(size_t)BB * HH];
__device__ __align__(16) __half g_da[(size_t)BB * HH];   // d2, then reused for d0
__device__ __align__(16) __half g_d1[(size_t)BB * HH];
// Weights. Forward needs W^T ([N,K] K-major); backward needs W direct ([N,K]).
__device__ __align__(16) __half g_W0T[HH * DD];          // [512,64]
__device__ __align__(16) __half g_W1T[HH * HH];
__device__ __align__(16) __half g_W2T[HH * HH];
__device__ __align__(16) __half g_W1 [HH * HH];
__device__ __align__(16) __half g_W2 [HH * HH];
__device__ __align__(16) __half g_W0 [DD * HH];          // [64,512]

// ---------------- helpers (all base-target PTX: sm_80-era) ----------------
__device__ __forceinline__ uint32_t smem_u32(const void* p) {
    uint32_t a;
    asm("{ .reg .u64 t; cvta.to.shared.u64 t, %1; cvt.u32.u64 %0, t; }" : "=r"(a) : "l"(p));
    return a;
}
__device__ __forceinline__ void cp16(uint32_t s, const void* g) {
    asm volatile("cp.async.cg.shared.global [%0], [%1], 16;" :: "r"(s), "l"(g));
}
#define CP_COMMIT() asm volatile("cp.async.commit_group;" ::: "memory")
#define CP_WAIT0()  asm volatile("cp.async.wait_group 0;" ::: "memory")

#define LDSM4(R, addr)                                                                   \
    asm volatile("ldmatrix.sync.aligned.m8n8.x4.shared.b16 {%0,%1,%2,%3}, [%4];"         \
        : "=r"((R)[0]), "=r"((R)[1]), "=r"((R)[2]), "=r"((R)[3]) : "r"(addr))

#define MMAH(C, A, b0_, b1_)                                                             \
    asm volatile("mma.sync.aligned.m16n8k16.row.col.f32.f16.f16.f32 "                    \
        "{%0,%1,%2,%3},{%4,%5,%6,%7},{%8,%9},{%0,%1,%2,%3};"                             \
        : "+f"((C)[0]), "+f"((C)[1]), "+f"((C)[2]), "+f"((C)[3])                         \
        : "r"((A)[0]), "r"((A)[1]), "r"((A)[2]), "r"((A)[3]), "r"(b0_), "r"(b1_))

__device__ __forceinline__ float tanh_fast(float x) {
    float e = __expf(2.0f * x);
    return 1.0f - __fdividef(2.0f, e + 1.0f);
}
__device__ __forceinline__ float sech2_of(float z) {   // 1 - tanh(z)^2
    float e = __expf(2.0f * z);
    float s = __fdividef(2.0f, e + 1.0f);              // s = 1 - tanh
    return s * (2.0f - s);
}
__device__ __forceinline__ uint32_t pack_h2(float a, float b) {
    __half2 h = __floats2half2_rn(a, b);
    return *reinterpret_cast<uint32_t*>(&h);
}
__device__ __forceinline__ float h2lo(uint32_t u) {
    return __half2float(__ushort_as_half((unsigned short)(u & 0xFFFF)));
}
__device__ __forceinline__ float h2hi(uint32_t u) {
    return __half2float(__ushort_as_half((unsigned short)(u >> 16)));
}

// ---------------- prep kernels: fp32 -> fp16 ----------------
__global__ void half_direct(const float* __restrict__ src, __half* __restrict__ dst, int n) {
    int i = blockIdx.x * blockDim.x + threadIdx.x;
    if (i < n) dst[i] = __float2half_rn(src[i]);
}
__global__ void half_trans(const float* __restrict__ src, __half* __restrict__ dst,
                           int R, int C) {
    int i = blockIdx.x * blockDim.x + threadIdx.x;
    if (i < R * C) {
        int r = i / C, c = i % C;
        dst[(size_t)c * R + r] = __float2half_rn(src[i]);
    }
}

// ---------------- stage loader: global -> padded smem via cp.async ----------------
// Smem rows: 32 fp16 (64B data) padded to 80B (20 words -> conflict-free ldmatrix).
template<int BN>
__device__ __forceinline__ void load_stage(
    uint32_t base_u, int buf,
    const __half* __restrict__ A, const __half* __restrict__ B,
    int bm, int bn, int K, int k0, int tid)
{
    constexpr int ASZ = 128 * 80;
    constexpr int BSZ = BN * 80;
    constexpr int STAGE = ASZ + BSZ;
    uint32_t sb = base_u + (uint32_t)(buf * STAGE);
#pragma unroll
    for (int i = tid; i < 128 * 4; i += 256) {
        int r = i >> 2, cc = i & 3;
        cp16(sb + (uint32_t)(r * 80 + cc * 16), A + (size_t)(bm + r) * K + k0 + cc * 8);
    }
#pragma unroll
    for (int i = tid; i < BN * 4; i += 256) {
        int r = i >> 2, cc = i & 3;
        cp16(sb + (uint32_t)(ASZ + r * 80 + cc * 16), B + (size_t)(bn + r) * K + k0 + cc * 8);
    }
}

// ---------------- fused fp16 HMMA GEMM (4 buffers, 2 stages per iteration) --------
// C[m,n] = sum_k A[m,k]*B[n,k], fp16 operands, fp32 accum.
// MODE 0: h = tanh(v + bias[n])                 -> O (fp16)
// MODE 1: out = w3[n]*(1 - tanh^2(v+bias[n]))   -> O (fp16)
// MODE 2: g = G[m,n]; out = v*(1-g^2)           -> O (fp16)
// MODE 3: symplectic fp32 write                 -> Of [B,64]
template<int MODE, int BN, int WARPS_M>
__global__ void __launch_bounds__(256)
hnn_mma(const __half* __restrict__ A, const __half* __restrict__ B,
        const float* __restrict__ bias, const float* __restrict__ w3,
        const __half* __restrict__ G, __half* __restrict__ O,
        float* __restrict__ Of, int K)
{
    constexpr int WARPS_N = 8 / WARPS_M;
    constexpr int WM = 128 / WARPS_M;          // 32 (BN=128) or 16 (BN=64)
    constexpr int WN = BN / WARPS_N;           // 64
    constexpr int MI = WM / 16;                // 2 or 1
    constexpr int NI = WN / 8;                 // 8
    constexpr int ASZ = 128 * 80;
    constexpr int BSZ = BN * 80;
    constexpr int STAGE = ASZ + BSZ;

    extern __shared__ char sm[];
    const uint32_t base_u = smem_u32(sm);
    const int tid = threadIdx.x;
    const int lane = tid & 31;
    const int wid = tid >> 5;
    const int wm = wid % WARPS_M;
    const int wn = wid / WARPS_M;
    const int bm = blockIdx.y * 128;
    const int bn = blockIdx.x * BN;
    const int NK2 = K >> 6;                    // iterations of 2 stages (64 K each)

    float acc[MI][NI][4];
#pragma unroll
    for (int mi = 0; mi < MI; mi++)
#pragma unroll
        for (int ni = 0; ni < NI; ni++)
#pragma unroll
            for (int r = 0; r < 4; r++) acc[mi][ni][r] = 0.0f;

    // prologue: prefetch stages 0 and 1
    load_stage<BN>(base_u, 0, A, B, bm, bn, K, 0, tid);
    CP_COMMIT();
    load_stage<BN>(base_u, 1, A, B, bm, bn, K, 32, tid);
    CP_COMMIT();

    for (int j = 0; j < NK2; j++) {
        CP_WAIT0();                  // stages 2j, 2j+1 resident
        __syncthreads();             // single barrier per 64 K

        // prefetch stages 2j+2, 2j+3 into the buffers computed in iter j-1.
        // Safe: every thread finished iter j-1 compute before this barrier.
        if (j + 1 < NK2) {
            load_stage<BN>(base_u, (2 * j + 2) & 3, A, B, bm, bn, K, (2 * j + 2) << 5, tid);
            CP_COMMIT();
            load_stage<BN>(base_u, (2 * j + 3) & 3, A, B, bm, bn, K, (2 * j + 3) << 5, tid);
            CP_COMMIT();
        }

#pragma unroll
        for (int half = 0; half < 2; half++) {           // the two resident stages
            const uint32_t sb = base_u + (uint32_t)(((2 * j + half) & 3) * STAGE);
#pragma unroll
            for (int kk = 0; kk < 2; kk++) {
                const int kb = kk * 16;
                uint32_t af[MI][4];
#pragma unroll
                for (int mi = 0; mi < MI; mi++) {
                    uint32_t addr = sb + (uint32_t)((wm * WM + mi * 16 + (lane & 15)) * 80 +
                                                    (kb + (lane >> 4) * 8) * 2);
                    LDSM4(af[mi], addr);
                }
#pragma unroll
                for (int n2 = 0; n2 < NI / 2; n2++) {
                    uint32_t baddr = sb + (uint32_t)(ASZ +
                        (wn * WN + n2 * 16 + ((lane >> 4) << 3) + (lane & 7)) * 80 +
                        (kb + ((lane >> 3) & 1) * 8) * 2);
                    uint32_t bf[4];
                    LDSM4(bf, baddr);
#pragma unroll
                    for (int mi = 0; mi < MI; mi++) {
                        MMAH(acc[mi][2 * n2],     af[mi], bf[0], bf[1]);
                        MMAH(acc[mi][2 * n2 + 1], af[mi], bf[2], bf[3]);
                    }
                }
            }
        }
        // no trailing barrier: next iteration's loads are issued only after its
        // barrier, which orders them against this iteration's compute.
    }

    // -------- fused epilogue --------
#pragma unroll
    for (int mi = 0; mi < MI; mi++) {
#pragma unroll
        for (int ni = 0; ni < NI; ni++) {
            float c0 = acc[mi][ni][0], c1 = acc[mi][ni][1];
            float c2 = acc[mi][ni][2], c3 = acc[mi][ni][3];
            const int gn = bn + wn * WN + ni * 8 + (lane & 3) * 2;
            const int r0 = bm + wm * WM + mi * 16 + (lane >> 2);
            const int r1 = r0 + 8;

            if (MODE == 0 || MODE == 1) {
                const float bb0 = bias[gn], bb1 = bias[gn + 1];
                float v0, v1, v2, v3;
                if (MODE == 0) {
                    v0 = tanh_fast(c0 + bb0); v1 = tanh_fast(c1 + bb1);
                    v2 = tanh_fast(c2 + bb0); v3 = tanh_fast(c3 + bb1);
                } else {
                    const float w0 = w3[gn], w1 = w3[gn + 1];
                    v0 = w0 * sech2_of(c0 + bb0); v1 = w1 * sech2_of(c1 + bb1);
                    v2 = w0 * sech2_of(c2 + bb0); v3 = w1 * sech2_of(c3 + bb1);
                }
                *reinterpret_cast<uint32_t*>(O + (size_t)r0 * HH + gn) = pack_h2(v0, v1);
                *reinterpret_cast<uint32_t*>(O + (size_t)r1 * HH + gn) = pack_h2(v2, v3);
            } else if (MODE == 2) {
                uint32_t gw0 = *reinterpret_cast<const uint32_t*>(G + (size_t)r0 * HH + gn);
                uint32_t gw1 = *reinterpret_cast<const uint32_t*>(G + (size_t)r1 * HH + gn);
                float ga = h2lo(gw0), gb = h2hi(gw0);
                float gc = h2lo(gw1), gd = h2hi(gw1);
                float v0 = c0 * (1.0f - ga * ga), v1 = c1 * (1.0f - gb * gb);
                float v2 = c2 * (1.0f - gc * gc), v3 = c3 * (1.0f - gd * gd);
                *reinterpret_cast<uint32_t*>(O + (size_t)r0 * HH + gn) = pack_h2(v0, v1);
                *reinterpret_cast<uint32_t*>(O + (size_t)r1 * HH + gn) = pack_h2(v2, v3);
            } else { // MODE 3: out[:,0:32] = grad[:,32:64]; out[:,32:64] = -grad[:,0:32]
                const int dc = (gn >= 32) ? gn - 32 : gn + 32;
                const float sgn = (gn >= 32) ? 1.0f : -1.0f;
                float2 t0; t0.x = sgn * c0; t0.y = sgn * c1;
                float2 t1; t1.x = sgn * c2; t1.y = sgn * c3;
                *reinterpret_cast<float2*>(Of + (size_t)r0 * DD + dc) = t0;
                *reinterpret_cast<float2*>(Of + (size_t)r1 * DD + dc) = t1;
            }
        }
    }
}

// ---------------- host ----------------
extern "C" void kernel_launch(void* const* d_in, const int* in_sizes, int n_in,
                              void* d_out, int out_size)
{
    const float* x  = (const float*)d_in[1];
    const float* W0 = (const float*)d_in[2];
    const float* b0 = (const float*)d_in[3];
    const float* W1 = (const float*)d_in[4];
    const float* b1 = (const float*)d_in[5];
    const float* W2 = (const float*)d_in[6];
    const float* b2 = (const float*)d_in[7];
    const float* W3 = (const float*)d_in[8];
    float* out = (float*)d_out;

    __half *xq, *h0, *h1, *da, *d1;
    __half *W0T, *W1T, *W2T, *W1q, *W2q, *W0q;
    cudaGetSymbolAddress((void**)&xq,  g_x);
    cudaGetSymbolAddress((void**)&h0,  g_h0);
    cudaGetSymbolAddress((void**)&h1,  g_h1);
    cudaGetSymbolAddress((void**)&da,  g_da);
    cudaGetSymbolAddress((void**)&d1,  g_d1);
    cudaGetSymbolAddress((void**)&W0T, g_W0T);
    cudaGetSymbolAddress((void**)&W1T, g_W1T);
    cudaGetSymbolAddress((void**)&W2T, g_W2T);
    cudaGetSymbolAddress((void**)&W1q, g_W1);
    cudaGetSymbolAddress((void**)&W2q, g_W2);
    cudaGetSymbolAddress((void**)&W0q, g_W0);

    // Stage bytes: A (128*80) + B (BN*80); 4 buffers.
    constexpr int SM128 = 4 * (128 * 80 + 128 * 80);   // 81920 -> 2 CTAs/SM
    constexpr int SM64  = 4 * (128 * 80 + 64 * 80);    // 61440
    cudaFuncSetAttribute(hnn_mma<0, 128, 4>, cudaFuncAttributeMaxDynamicSharedMemorySize, SM128);
    cudaFuncSetAttribute(hnn_mma<1, 128, 4>, cudaFuncAttributeMaxDynamicSharedMemorySize, SM128);
    cudaFuncSetAttribute(hnn_mma<2, 128, 4>, cudaFuncAttributeMaxDynamicSharedMemorySize, SM128);
    cudaFuncSetAttribute(hnn_mma<3, 64, 8>,  cudaFuncAttributeMaxDynamicSharedMemorySize, SM64);

    // ---- prep: convert/transpose operands into fp16 ----
    {
        int n;
        n = BB * DD; half_direct<<<(n + 255) / 256, 256>>>(x, xq, n);
        n = DD * HH; half_direct<<<(n + 255) / 256, 256>>>(W0, W0q, n);
        half_trans<<<(n + 255) / 256, 256>>>(W0, W0T, DD, HH);
        n = HH * HH;
        half_direct<<<(n + 255) / 256, 256>>>(W1, W1q, n);
        half_direct<<<(n + 255) / 256, 256>>>(W2, W2q, n);
        half_trans<<<(n + 255) / 256, 256>>>(W1, W1T, HH, HH);
        half_trans<<<(n + 255) / 256, 256>>>(W2, W2T, HH, HH);
    }

    const dim3 gH(HH / 128, BB / 128);   // (4, 512)
    const dim3 gO(1,        BB / 128);   // (1, 512)

    // 1) h0 = tanh(x @ W0 + b0)
    hnn_mma<0, 128, 4><<<gH, 256, SM128>>>(xq, W0T, b0, nullptr, nullptr, h0, nullptr, DD);
    // 2) h1 = tanh(h0 @ W1 + b1)
    hnn_mma<0, 128, 4><<<gH, 256, SM128>>>(h0, W1T, b1, nullptr, nullptr, h1, nullptr, HH);
    // 3) d2 = W3 * (1 - tanh^2(h1 @ W2 + b2))
    hnn_mma<1, 128, 4><<<gH, 256, SM128>>>(h1, W2T, b2, W3, nullptr, da, nullptr, HH);
    // 4) d1 = (d2 @ W2^T) * (1 - h1^2)
    hnn_mma<2, 128, 4><<<gH, 256, SM128>>>(da, W2q, nullptr, nullptr, h1, d1, nullptr, HH);
    // 5) d0 = (d1 @ W1^T) * (1 - h0^2)   (reuse da buffer)
    hnn_mma<2, 128, 4><<<gH, 256, SM128>>>(d1, W1q, nullptr, nullptr, h0, da, nullptr, HH);
    // 6) out = symplectic(d0 @ W0^T)
    hnn_mma<3, 64, 8><<<gO, 256, SM64>>>(da, W0q, nullptr, nullptr, nullptr, nullptr, out, HH);
}

// round 16
// speedup vs baseline: 4.6538x; 1.0350x over previous
#include <cuda_runtime.h>
#include <cuda_fp16.h>
#include <cstdint>
#include <math.h>

static constexpr int BB = 65536;
static constexpr int DD = 64;
static constexpr int HH = 512;

// ---------------- scratch (__device__ globals; allocation-free rule) -------------
__device__ __align__(16) __half g_x [(size_t)BB * DD];
__device__ __align__(16) __half g_h0[(size_t)BB * HH];
__device__ __align__(16) __half g_h1[(size_t)BB * HH];
__device__ __align__(16) __half g_da[(size_t)BB * HH];   // d2, then reused for d0
__device__ __align__(16) __half g_d1[(size_t)BB * HH];
// Weights. Forward needs W^T ([N,K] K-major); backward needs W direct ([N,K]).
__device__ __align__(16) __half g_W0T[HH * DD];          // [512,64]
__device__ __align__(16) __half g_W1T[HH * HH];
__device__ __align__(16) __half g_W2T[HH * HH];
__device__ __align__(16) __half g_W1 [HH * HH];
__device__ __align__(16) __half g_W2 [HH * HH];
__device__ __align__(16) __half g_W0 [DD * HH];          // [64,512]

// ---------------- helpers (all base-target PTX: sm_80-era) ----------------
__device__ __forceinline__ uint32_t smem_u32(const void* p) {
    uint32_t a;
    asm("{ .reg .u64 t; cvta.to.shared.u64 t, %1; cvt.u32.u64 %0, t; }" : "=r"(a) : "l"(p));
    return a;
}
__device__ __forceinline__ void cp16(uint32_t s, const void* g) {
    asm volatile("cp.async.cg.shared.global [%0], [%1], 16;" :: "r"(s), "l"(g));
}
#define CP_COMMIT() asm volatile("cp.async.commit_group;" ::: "memory")
#define CP_WAIT2()  asm volatile("cp.async.wait_group 2;" ::: "memory")
#define CP_WAIT0()  asm volatile("cp.async.wait_group 0;" ::: "memory")

#define LDSM4(R, addr)                                                                   \
    asm volatile("ldmatrix.sync.aligned.m8n8.x4.shared.b16 {%0,%1,%2,%3}, [%4];"         \
        : "=r"((R)[0]), "=r"((R)[1]), "=r"((R)[2]), "=r"((R)[3]) : "r"(addr))

#define MMAH(C, A, b0_, b1_)                                                             \
    asm volatile("mma.sync.aligned.m16n8k16.row.col.f32.f16.f16.f32 "                    \
        "{%0,%1,%2,%3},{%4,%5,%6,%7},{%8,%9},{%0,%1,%2,%3};"                             \
        : "+f"((C)[0]), "+f"((C)[1]), "+f"((C)[2]), "+f"((C)[3])                         \
        : "r"((A)[0]), "r"((A)[1]), "r"((A)[2]), "r"((A)[3]), "r"(b0_), "r"(b1_))

__device__ __forceinline__ float tanh_fast(float x) {
    float e = __expf(2.0f * x);
    return 1.0f - __fdividef(2.0f, e + 1.0f);
}
__device__ __forceinline__ float sech2_of(float z) {   // 1 - tanh(z)^2
    float e = __expf(2.0f * z);
    float s = __fdividef(2.0f, e + 1.0f);              // s = 1 - tanh
    return s * (2.0f - s);
}
__device__ __forceinline__ uint32_t pack_h2(float a, float b) {
    __half2 h = __floats2half2_rn(a, b);
    return *reinterpret_cast<uint32_t*>(&h);
}
__device__ __forceinline__ float h2lo(uint32_t u) {
    return __half2float(__ushort_as_half((unsigned short)(u & 0xFFFF)));
}
__device__ __forceinline__ float h2hi(uint32_t u) {
    return __half2float(__ushort_as_half((unsigned short)(u >> 16)));
}

// ---------------- prep kernels ----------------
// x: fp32 -> fp16 (memory-bound, standalone)
__global__ void half_direct(const float* __restrict__ src, __half* __restrict__ dst, int n) {
    int i = blockIdx.x * blockDim.x + threadIdx.x;
    if (i < n) dst[i] = __float2half_rn(src[i]);
}
// All weights in ONE launch: each thread converts one fp32 element and writes
// both the direct and the transposed fp16 copy. Replaces 6 tiny launches.
static constexpr int NW0 = DD * HH;            // 32768
static constexpr int NWH = HH * HH;            // 262144
__global__ void prep_weights(const float* __restrict__ W0, const float* __restrict__ W1,
                             const float* __restrict__ W2,
                             __half* __restrict__ W0q, __half* __restrict__ W0T,
                             __half* __restrict__ W1q, __half* __restrict__ W1T,
                             __half* __restrict__ W2q, __half* __restrict__ W2T) {
    int i = blockIdx.x * blockDim.x + threadIdx.x;
    if (i < NW0) {                                    // W0 [64,512]
        int r = i >> 9, c = i & 511;
        __half h = __float2half_rn(W0[i]);
        W0q[i] = h;
        W0T[c * DD + r] = h;
    } else if (i < NW0 + NWH) {                       // W1 [512,512]
        int j = i - NW0;
        int r = j >> 9, c = j & 511;
        __half h = __float2half_rn(W1[j]);
        W1q[j] = h;
        W1T[c * HH + r] = h;
    } else if (i < NW0 + 2 * NWH) {                   // W2 [512,512]
        int j = i - NW0 - NWH;
        int r = j >> 9, c = j & 511;
        __half h = __float2half_rn(W2[j]);
        W2q[j] = h;
        W2T[c * HH + r] = h;
    }
}

// ---------------- stage loader: global -> padded smem via cp.async ----------------
// Smem rows: 32 fp16 (64B data) padded to 80B (20 words -> conflict-free ldmatrix).
template<int BN>
__device__ __forceinline__ void load_stage(
    uint32_t base_u, int buf,
    const __half* __restrict__ A, const __half* __restrict__ B,
    int bm, int bn, int K, int k0, int tid)
{
    constexpr int ASZ = 128 * 80;
    constexpr int BSZ = BN * 80;
    constexpr int STAGE = ASZ + BSZ;
    uint32_t sb = base_u + (uint32_t)(buf * STAGE);
#pragma unroll
    for (int i = tid; i < 128 * 4; i += 256) {
        int r = i >> 2, cc = i & 3;
        cp16(sb + (uint32_t)(r * 80 + cc * 16), A + (size_t)(bm + r) * K + k0 + cc * 8);
    }
#pragma unroll
    for (int i = tid; i < BN * 4; i += 256) {
        int r = i >> 2, cc = i & 3;
        cp16(sb + (uint32_t)(ASZ + r * 80 + cc * 16), B + (size_t)(bn + r) * K + k0 + cc * 8);
    }
}

// ---------------- fused fp16 HMMA GEMM (4-stage, distance-2 pipeline) -------------
// C[m,n] = sum_k A[m,k]*B[n,k], fp16 operands, fp32 accum.
// MODE 0: h = tanh(v + bias[n])                 -> O (fp16)
// MODE 1: out = w3[n]*(1 - tanh^2(v+bias[n]))   -> O (fp16)
// MODE 2: g = G[m,n]; out = v*(1-g^2)           -> O (fp16)
// MODE 3: symplectic fp32 write                 -> Of [B,64]
template<int MODE, int BN, int WARPS_M>
__global__ void __launch_bounds__(256)
hnn_mma(const __half* __restrict__ A, const __half* __restrict__ B,
        const float* __restrict__ bias, const float* __restrict__ w3,
        const __half* __restrict__ G, __half* __restrict__ O,
        float* __restrict__ Of, int K)
{
    constexpr int WARPS_N = 8 / WARPS_M;
    constexpr int WM = 128 / WARPS_M;          // 32 (BN=128) or 16 (BN=64)
    constexpr int WN = BN / WARPS_N;           // 64
    constexpr int MI = WM / 16;                // 2 or 1
    constexpr int NI = WN / 8;                 // 8
    constexpr int ASZ = 128 * 80;
    constexpr int BSZ = BN * 80;
    constexpr int STAGE = ASZ + BSZ;

    extern __shared__ char sm[];
    const uint32_t base_u = smem_u32(sm);
    const int tid = threadIdx.x;
    const int lane = tid & 31;
    const int wid = tid >> 5;
    const int wm = wid % WARPS_M;
    const int wn = wid / WARPS_M;
    const int bm = blockIdx.y * 128;
    const int bn = blockIdx.x * BN;
    const int NK = K >> 5;

    float acc[MI][NI][4];
#pragma unroll
    for (int mi = 0; mi < MI; mi++)
#pragma unroll
        for (int ni = 0; ni < NI; ni++)
#pragma unroll
            for (int r = 0; r < 4; r++) acc[mi][ni][r] = 0.0f;

    // prologue: prefetch stages 0 and 1 (distance 2, 4 buffers)
    load_stage<BN>(base_u, 0, A, B, bm, bn, K, 0, tid);
    CP_COMMIT();
    if (NK > 1) load_stage<BN>(base_u, 1, A, B, bm, bn, K, 32, tid);
    CP_COMMIT();

    for (int ks = 0; ks < NK; ks++) {
        // issue stage ks+2 (buffer (ks+2)&3 == (ks-2)&3, compute done before the
        // barrier of iteration ks-1 -> single barrier per iteration is safe)
        if (ks + 2 < NK)
            load_stage<BN>(base_u, (ks + 2) & 3, A, B, bm, bn, K, (ks + 2) << 5, tid);
        CP_COMMIT();                 // one group per iteration (possibly empty)
        CP_WAIT2();                  // oldest pending (stage ks) complete
        __syncthreads();

        const uint32_t sb = base_u + (uint32_t)((ks & 3) * STAGE);
#pragma unroll
        for (int kk = 0; kk < 2; kk++) {
            const int kb = kk * 16;
            uint32_t af[MI][4];
#pragma unroll
            for (int mi = 0; mi < MI; mi++) {
                uint32_t addr = sb + (uint32_t)((wm * WM + mi * 16 + (lane & 15)) * 80 +
                                                (kb + (lane >> 4) * 8) * 2);
                LDSM4(af[mi], addr);
            }
#pragma unroll
            for (int n2 = 0; n2 < NI / 2; n2++) {
                uint32_t baddr = sb + (uint32_t)(ASZ +
                    (wn * WN + n2 * 16 + ((lane >> 4) << 3) + (lane & 7)) * 80 +
                    (kb + ((lane >> 3) & 1) * 8) * 2);
                uint32_t bf[4];
                LDSM4(bf, baddr);
#pragma unroll
                for (int mi = 0; mi < MI; mi++) {
                    MMAH(acc[mi][2 * n2],     af[mi], bf[0], bf[1]);
                    MMAH(acc[mi][2 * n2 + 1], af[mi], bf[2], bf[3]);
                }
            }
        }
        // no trailing barrier (4-buffer / distance-2 invariant)
    }

    // -------- fused epilogue --------
#pragma unroll
    for (int mi = 0; mi < MI; mi++) {
#pragma unroll
        for (int ni = 0; ni < NI; ni++) {
            float c0 = acc[mi][ni][0], c1 = acc[mi][ni][1];
            float c2 = acc[mi][ni][2], c3 = acc[mi][ni][3];
            const int gn = bn + wn * WN + ni * 8 + (lane & 3) * 2;
            const int r0 = bm + wm * WM + mi * 16 + (lane >> 2);
            const int r1 = r0 + 8;

            if (MODE == 0 || MODE == 1) {
                const float bb0 = bias[gn], bb1 = bias[gn + 1];
                float v0, v1, v2, v3;
                if (MODE == 0) {
                    v0 = tanh_fast(c0 + bb0); v1 = tanh_fast(c1 + bb1);
                    v2 = tanh_fast(c2 + bb0); v3 = tanh_fast(c3 + bb1);
                } else {
                    const float w0 = w3[gn], w1 = w3[gn + 1];
                    v0 = w0 * sech2_of(c0 + bb0); v1 = w1 * sech2_of(c1 + bb1);
                    v2 = w0 * sech2_of(c2 + bb0); v3 = w1 * sech2_of(c3 + bb1);
                }
                *reinterpret_cast<uint32_t*>(O + (size_t)r0 * HH + gn) = pack_h2(v0, v1);
                *reinterpret_cast<uint32_t*>(O + (size_t)r1 * HH + gn) = pack_h2(v2, v3);
            } else if (MODE == 2) {
                uint32_t gw0 = *reinterpret_cast<const uint32_t*>(G + (size_t)r0 * HH + gn);
                uint32_t gw1 = *reinterpret_cast<const uint32_t*>(G + (size_t)r1 * HH + gn);
                float ga = h2lo(gw0), gb = h2hi(gw0);
                float gc = h2lo(gw1), gd = h2hi(gw1);
                float v0 = c0 * (1.0f - ga * ga), v1 = c1 * (1.0f - gb * gb);
                float v2 = c2 * (1.0f - gc * gc), v3 = c3 * (1.0f - gd * gd);
                *reinterpret_cast<uint32_t*>(O + (size_t)r0 * HH + gn) = pack_h2(v0, v1);
                *reinterpret_cast<uint32_t*>(O + (size_t)r1 * HH + gn) = pack_h2(v2, v3);
            } else { // MODE 3: out[:,0:32] = grad[:,32:64]; out[:,32:64] = -grad[:,0:32]
                const int dc = (gn >= 32) ? gn - 32 : gn + 32;
                const float sgn = (gn >= 32) ? 1.0f : -1.0f;
                float2 t0; t0.x = sgn * c0; t0.y = sgn * c1;
                float2 t1; t1.x = sgn * c2; t1.y = sgn * c3;
                *reinterpret_cast<float2*>(Of + (size_t)r0 * DD + dc) = t0;
                *reinterpret_cast<float2*>(Of + (size_t)r1 * DD + dc) = t1;
            }
        }
    }
}

// ---------------- host ----------------
extern "C" void kernel_launch(void* const* d_in, const int* in_sizes, int n_in,
                              void* d_out, int out_size)
{
    const float* x  = (const float*)d_in[1];
    const float* W0 = (const float*)d_in[2];
    const float* b0 = (const float*)d_in[3];
    const float* W1 = (const float*)d_in[4];
    const float* b1 = (const float*)d_in[5];
    const float* W2 = (const float*)d_in[6];
    const float* b2 = (const float*)d_in[7];
    const float* W3 = (const float*)d_in[8];
    float* out = (float*)d_out;

    __half *xq, *h0, *h1, *da, *d1;
    __half *W0T, *W1T, *W2T, *W1q, *W2q, *W0q;
    cudaGetSymbolAddress((void**)&xq,  g_x);
    cudaGetSymbolAddress((void**)&h0,  g_h0);
    cudaGetSymbolAddress((void**)&h1,  g_h1);
    cudaGetSymbolAddress((void**)&da,  g_da);
    cudaGetSymbolAddress((void**)&d1,  g_d1);
    cudaGetSymbolAddress((void**)&W0T, g_W0T);
    cudaGetSymbolAddress((void**)&W1T, g_W1T);
    cudaGetSymbolAddress((void**)&W2T, g_W2T);
    cudaGetSymbolAddress((void**)&W1q, g_W1);
    cudaGetSymbolAddress((void**)&W2q, g_W2);
    cudaGetSymbolAddress((void**)&W0q, g_W0);

    // Stage bytes: A (128*80) + B (BN*80); 4 buffers.
    constexpr int SM128 = 4 * (128 * 80 + 128 * 80);   // 81920 -> 2 CTAs/SM
    constexpr int SM64  = 4 * (128 * 80 + 64 * 80);    // 61440
    cudaFuncSetAttribute(hnn_mma<0, 128, 4>, cudaFuncAttributeMaxDynamicSharedMemorySize, SM128);
    cudaFuncSetAttribute(hnn_mma<1, 128, 4>, cudaFuncAttributeMaxDynamicSharedMemorySize, SM128);
    cudaFuncSetAttribute(hnn_mma<2, 128, 4>, cudaFuncAttributeMaxDynamicSharedMemorySize, SM128);
    cudaFuncSetAttribute(hnn_mma<3, 64, 8>,  cudaFuncAttributeMaxDynamicSharedMemorySize, SM64);

    // ---- prep: 2 launches (x convert; all weights fused) ----
    {
        int n = BB * DD;
        half_direct<<<(n + 255) / 256, 256>>>(x, xq, n);
        int nw = NW0 + 2 * NWH;                      // 557056
        prep_weights<<<(nw + 255) / 256, 256>>>(W0, W1, W2,
                                                W0q, W0T, W1q, W1T, W2q, W2T);
    }

    const dim3 gH(HH / 128, BB / 128);   // (4, 512)
    const dim3 gO(1,        BB / 128);   // (1, 512)

    // 1) h0 = tanh(x @ W0 + b0)
    hnn_mma<0, 128, 4><<<gH, 256, SM128>>>(xq, W0T, b0, nullptr, nullptr, h0, nullptr, DD);
    // 2) h1 = tanh(h0 @ W1 + b1)
    hnn_mma<0, 128, 4><<<gH, 256, SM128>>>(h0, W1T, b1, nullptr, nullptr, h1, nullptr, HH);
    // 3) d2 = W3 * (1 - tanh^2(h1 @ W2 + b2))
    hnn_mma<1, 128, 4><<<gH, 256, SM128>>>(h1, W2T, b2, W3, nullptr, da, nullptr, HH);
    // 4) d1 = (d2 @ W2^T) * (1 - h1^2)
    hnn_mma<2, 128, 4><<<gH, 256, SM128>>>(da, W2q, nullptr, nullptr, h1, d1, nullptr, HH);
    // 5) d0 = (d1 @ W1^T) * (1 - h0^2)   (reuse da buffer)
    hnn_mma<2, 128, 4><<<gH, 256, SM128>>>(d1, W1q, nullptr, nullptr, h0, da, nullptr, HH);
    // 6) out = symplectic(d0 @ W0^T)
    hnn_mma<3, 64, 8><<<gO, 256, SM64>>>(da, W0q, nullptr, nullptr, nullptr, nullptr, out, HH);
}

// round 17
// speedup vs baseline: 4.8719x; 1.0469x over previous
#include <cuda_runtime.h>
#include <cuda_fp16.h>
#include <cstdint>
#include <math.h>

static constexpr int BB = 65536;
static constexpr int DD = 64;
static constexpr int HH = 512;

// ---------------- scratch (__device__ globals; allocation-free rule) -------------
__device__ __align__(16) __half g_x [(size_t)BB * DD];
__device__ __align__(16) __half g_h0[(size_t)BB * HH];
__device__ __align__(16) __half g_h1[(size_t)BB * HH];
__device__ __align__(16) __half g_da[(size_t)BB * HH];   // d2, then reused for d0
__device__ __align__(16) __half g_d1[(size_t)BB * HH];
// Weights. Forward needs W^T ([N,K] K-major); backward needs W direct ([N,K]).
__device__ __align__(16) __half g_W0T[HH * DD];          // [512,64]
__device__ __align__(16) __half g_W1T[HH * HH];
__device__ __align__(16) __half g_W2T[HH * HH];
__device__ __align__(16) __half g_W1 [HH * HH];
__device__ __align__(16) __half g_W2 [HH * HH];
__device__ __align__(16) __half g_W0 [DD * HH];          // [64,512]

// ---------------- helpers (all base-target PTX: sm_80-era) ----------------
__device__ __forceinline__ uint32_t smem_u32(const void* p) {
    uint32_t a;
    asm("{ .reg .u64 t; cvta.to.shared.u64 t, %1; cvt.u32.u64 %0, t; }" : "=r"(a) : "l"(p));
    return a;
}
__device__ __forceinline__ void cp16(uint32_t s, const void* g) {
    asm volatile("cp.async.cg.shared.global [%0], [%1], 16;" :: "r"(s), "l"(g));
}
#define CP_COMMIT() asm volatile("cp.async.commit_group;" ::: "memory")
#define CP_WAIT2()  asm volatile("cp.async.wait_group 2;" ::: "memory")

#define LDSM4(R, addr)                                                                   \
    asm volatile("ldmatrix.sync.aligned.m8n8.x4.shared.b16 {%0,%1,%2,%3}, [%4];"         \
        : "=r"((R)[0]), "=r"((R)[1]), "=r"((R)[2]), "=r"((R)[3]) : "r"(addr))

#define MMAH(C, A, b0_, b1_)                                                             \
    asm volatile("mma.sync.aligned.m16n8k16.row.col.f32.f16.f16.f32 "                    \
        "{%0,%1,%2,%3},{%4,%5,%6,%7},{%8,%9},{%0,%1,%2,%3};"                             \
        : "+f"((C)[0]), "+f"((C)[1]), "+f"((C)[2]), "+f"((C)[3])                         \
        : "r"((A)[0]), "r"((A)[1]), "r"((A)[2]), "r"((A)[3]), "r"(b0_), "r"(b1_))

__device__ __forceinline__ float tanh_fast(float x) {
    float e = __expf(2.0f * x);
    return 1.0f - __fdividef(2.0f, e + 1.0f);
}
__device__ __forceinline__ float sech2_of(float z) {   // 1 - tanh(z)^2
    float e = __expf(2.0f * z);
    float s = __fdividef(2.0f, e + 1.0f);              // s = 1 - tanh
    return s * (2.0f - s);
}
__device__ __forceinline__ uint32_t pack_h2(float a, float b) {
    __half2 h = __floats2half2_rn(a, b);
    return *reinterpret_cast<uint32_t*>(&h);
}
__device__ __forceinline__ float h2lo(uint32_t u) {
    return __half2float(__ushort_as_half((unsigned short)(u & 0xFFFF)));
}
__device__ __forceinline__ float h2hi(uint32_t u) {
    return __half2float(__ushort_as_half((unsigned short)(u >> 16)));
}

// ---------------- prep kernels ----------------
__global__ void half_direct(const float* __restrict__ src, __half* __restrict__ dst, int n) {
    int i = blockIdx.x * blockDim.x + threadIdx.x;
    if (i < n) dst[i] = __float2half_rn(src[i]);
}
// All weights in ONE launch: convert one fp32 element, write direct + transposed fp16.
static constexpr int NW0 = DD * HH;            // 32768
static constexpr int NWH = HH * HH;            // 262144
__global__ void prep_weights(const float* __restrict__ W0, const float* __restrict__ W1,
                             const float* __restrict__ W2,
                             __half* __restrict__ W0q, __half* __restrict__ W0T,
                             __half* __restrict__ W1q, __half* __restrict__ W1T,
                             __half* __restrict__ W2q, __half* __restrict__ W2T) {
    int i = blockIdx.x * blockDim.x + threadIdx.x;
    if (i < NW0) {                                    // W0 [64,512]
        int r = i >> 9, c = i & 511;
        __half h = __float2half_rn(W0[i]);
        W0q[i] = h;
        W0T[c * DD + r] = h;
    } else if (i < NW0 + NWH) {                       // W1 [512,512]
        int j = i - NW0;
        int r = j >> 9, c = j & 511;
        __half h = __float2half_rn(W1[j]);
        W1q[j] = h;
        W1T[c * HH + r] = h;
    } else if (i < NW0 + 2 * NWH) {                   // W2 [512,512]
        int j = i - NW0 - NWH;
        int r = j >> 9, c = j & 511;
        __half h = __float2half_rn(W2[j]);
        W2q[j] = h;
        W2T[c * HH + r] = h;
    }
}

// ---------------- stage loader: global -> padded smem via cp.async ----------------
// Smem rows: 32 fp16 (64B data) padded to 80B (20 words -> conflict-free ldmatrix).
template<int BN>
__device__ __forceinline__ void load_stage(
    uint32_t base_u, int buf,
    const __half* __restrict__ A, const __half* __restrict__ B,
    int bm, int bn, int K, int k0, int tid)
{
    constexpr int ASZ = 128 * 80;
    constexpr int BSZ = BN * 80;
    constexpr int STAGE = ASZ + BSZ;
    uint32_t sb = base_u + (uint32_t)(buf * STAGE);
#pragma unroll
    for (int i = tid; i < 128 * 4; i += 256) {
        int r = i >> 2, cc = i & 3;
        cp16(sb + (uint32_t)(r * 80 + cc * 16), A + (size_t)(bm + r) * K + k0 + cc * 8);
    }
#pragma unroll
    for (int i = tid; i < BN * 4; i += 256) {
        int r = i >> 2, cc = i & 3;
        cp16(sb + (uint32_t)(ASZ + r * 80 + cc * 16), B + (size_t)(bn + r) * K + k0 + cc * 8);
    }
}

// ---------------- fused fp16 HMMA GEMM (4-stage, distance-2 pipeline) -------------
// C[m,n] = sum_k A[m,k]*B[n,k], fp16 operands, fp32 accum.
// Inner loop: batch ALL 6 LDSMs per kk before the 16 MMAs (asm volatile keeps
// source order; batching exposes one smem latency per kk instead of four).
// MODE 0: h = tanh(v + bias[n]) ; MODE 1: w3*(1-tanh^2) ; MODE 2: v*(1-g^2) ;
// MODE 3: symplectic fp32 write.
template<int MODE, int BN, int WARPS_M>
__global__ void __launch_bounds__(256)
hnn_mma(const __half* __restrict__ A, const __half* __restrict__ B,
        const float* __restrict__ bias, const float* __restrict__ w3,
        const __half* __restrict__ G, __half* __restrict__ O,
        float* __restrict__ Of, int K)
{
    constexpr int WARPS_N = 8 / WARPS_M;
    constexpr int WM = 128 / WARPS_M;          // 32 (BN=128) or 16 (BN=64)
    constexpr int WN = BN / WARPS_N;           // 64
    constexpr int MI = WM / 16;                // 2 or 1
    constexpr int NI = WN / 8;                 // 8
    constexpr int ASZ = 128 * 80;
    constexpr int BSZ = BN * 80;
    constexpr int STAGE = ASZ + BSZ;

    extern __shared__ char sm[];
    const uint32_t base_u = smem_u32(sm);
    const int tid = threadIdx.x;
    const int lane = tid & 31;
    const int wid = tid >> 5;
    const int wm = wid % WARPS_M;
    const int wn = wid / WARPS_M;
    const int bm = blockIdx.y * 128;
    const int bn = blockIdx.x * BN;
    const int NK = K >> 5;

    float acc[MI][NI][4];
#pragma unroll
    for (int mi = 0; mi < MI; mi++)
#pragma unroll
        for (int ni = 0; ni < NI; ni++)
#pragma unroll
            for (int r = 0; r < 4; r++) acc[mi][ni][r] = 0.0f;

    // per-warp invariant LDSM offsets (alu reduction; only sb varies per stage)
    uint32_t a_off[MI], b_off[NI / 2];
#pragma unroll
    for (int mi = 0; mi < MI; mi++)
        a_off[mi] = (uint32_t)((wm * WM + mi * 16 + (lane & 15)) * 80 + ((lane >> 4) * 8) * 2);
#pragma unroll
    for (int n2 = 0; n2 < NI / 2; n2++)
        b_off[n2] = (uint32_t)(ASZ + (wn * WN + n2 * 16 + ((lane >> 4) << 3) + (lane & 7)) * 80 +
                               (((lane >> 3) & 1) * 8) * 2);

    // prologue: prefetch stages 0 and 1 (distance 2, 4 buffers)
    load_stage<BN>(base_u, 0, A, B, bm, bn, K, 0, tid);
    CP_COMMIT();
    if (NK > 1) load_stage<BN>(base_u, 1, A, B, bm, bn, K, 32, tid);
    CP_COMMIT();

    for (int ks = 0; ks < NK; ks++) {
        if (ks + 2 < NK)
            load_stage<BN>(base_u, (ks + 2) & 3, A, B, bm, bn, K, (ks + 2) << 5, tid);
        CP_COMMIT();                 // one group per iteration (possibly empty)
        CP_WAIT2();                  // oldest pending (stage ks) complete
        __syncthreads();

        const uint32_t sb = base_u + (uint32_t)((ks & 3) * STAGE);
#pragma unroll
        for (int kk = 0; kk < 2; kk++) {
            const uint32_t kboff = (uint32_t)(kk * 32);      // 16 fp16 = 32 bytes
            uint32_t af[MI][4];
            uint32_t bf[NI / 2][4];
            // ---- all LDSMs first (pipelined in LSU; one exposed latency) ----
#pragma unroll
            for (int mi = 0; mi < MI; mi++)
                LDSM4(af[mi], sb + a_off[mi] + kboff);
#pragma unroll
            for (int n2 = 0; n2 < NI / 2; n2++)
                LDSM4(bf[n2], sb + b_off[n2] + kboff);
            // ---- then all MMAs ----
#pragma unroll
            for (int n2 = 0; n2 < NI / 2; n2++)
#pragma unroll
                for (int mi = 0; mi < MI; mi++) {
                    MMAH(acc[mi][2 * n2],     af[mi], bf[n2][0], bf[n2][1]);
                    MMAH(acc[mi][2 * n2 + 1], af[mi], bf[n2][2], bf[n2][3]);
                }
        }
        // no trailing barrier (4-buffer / distance-2 invariant)
    }

    // -------- fused epilogue --------
#pragma unroll
    for (int mi = 0; mi < MI; mi++) {
#pragma unroll
        for (int ni = 0; ni < NI; ni++) {
            float c0 = acc[mi][ni][0], c1 = acc[mi][ni][1];
            float c2 = acc[mi][ni][2], c3 = acc[mi][ni][3];
            const int gn = bn + wn * WN + ni * 8 + (lane & 3) * 2;
            const int r0 = bm + wm * WM + mi * 16 + (lane >> 2);
            const int r1 = r0 + 8;

            if (MODE == 0 || MODE == 1) {
                const float bb0 = bias[gn], bb1 = bias[gn + 1];
                float v0, v1, v2, v3;
                if (MODE == 0) {
                    v0 = tanh_fast(c0 + bb0); v1 = tanh_fast(c1 + bb1);
                    v2 = tanh_fast(c2 + bb0); v3 = tanh_fast(c3 + bb1);
                } else {
                    const float w0 = w3[gn], w1 = w3[gn + 1];
                    v0 = w0 * sech2_of(c0 + bb0); v1 = w1 * sech2_of(c1 + bb1);
                    v2 = w0 * sech2_of(c2 + bb0); v3 = w1 * sech2_of(c3 + bb1);
                }
                *reinterpret_cast<uint32_t*>(O + (size_t)r0 * HH + gn) = pack_h2(v0, v1);
                *reinterpret_cast<uint32_t*>(O + (size_t)r1 * HH + gn) = pack_h2(v2, v3);
            } else if (MODE == 2) {
                uint32_t gw0 = *reinterpret_cast<const uint32_t*>(G + (size_t)r0 * HH + gn);
                uint32_t gw1 = *reinterpret_cast<const uint32_t*>(G + (size_t)r1 * HH + gn);
                float ga = h2lo(gw0), gb = h2hi(gw0);
                float gc = h2lo(gw1), gd = h2hi(gw1);
                float v0 = c0 * (1.0f - ga * ga), v1 = c1 * (1.0f - gb * gb);
                float v2 = c2 * (1.0f - gc * gc), v3 = c3 * (1.0f - gd * gd);
                *reinterpret_cast<uint32_t*>(O + (size_t)r0 * HH + gn) = pack_h2(v0, v1);
                *reinterpret_cast<uint32_t*>(O + (size_t)r1 * HH + gn) = pack_h2(v2, v3);
            } else { // MODE 3: out[:,0:32] = grad[:,32:64]; out[:,32:64] = -grad[:,0:32]
                const int dc = (gn >= 32) ? gn - 32 : gn + 32;
                const float sgn = (gn >= 32) ? 1.0f : -1.0f;
                float2 t0; t0.x = sgn * c0; t0.y = sgn * c1;
                float2 t1; t1.x = sgn * c2; t1.y = sgn * c3;
                *reinterpret_cast<float2*>(Of + (size_t)r0 * DD + dc) = t0;
                *reinterpret_cast<float2*>(Of + (size_t)r1 * DD + dc) = t1;
            }
        }
    }
}

// ---------------- host ----------------
extern "C" void kernel_launch(void* const* d_in, const int* in_sizes, int n_in,
                              void* d_out, int out_size)
{
    const float* x  = (const float*)d_in[1];
    const float* W0 = (const float*)d_in[2];
    const float* b0 = (const float*)d_in[3];
    const float* W1 = (const float*)d_in[4];
    const float* b1 = (const float*)d_in[5];
    const float* W2 = (const float*)d_in[6];
    const float* b2 = (const float*)d_in[7];
    const float* W3 = (const float*)d_in[8];
    float* out = (float*)d_out;

    __half *xq, *h0, *h1, *da, *d1;
    __half *W0T, *W1T, *W2T, *W1q, *W2q, *W0q;
    cudaGetSymbolAddress((void**)&xq,  g_x);
    cudaGetSymbolAddress((void**)&h0,  g_h0);
    cudaGetSymbolAddress((void**)&h1,  g_h1);
    cudaGetSymbolAddress((void**)&da,  g_da);
    cudaGetSymbolAddress((void**)&d1,  g_d1);
    cudaGetSymbolAddress((void**)&W0T, g_W0T);
    cudaGetSymbolAddress((void**)&W1T, g_W1T);
    cudaGetSymbolAddress((void**)&W2T, g_W2T);
    cudaGetSymbolAddress((void**)&W1q, g_W1);
    cudaGetSymbolAddress((void**)&W2q, g_W2);
    cudaGetSymbolAddress((void**)&W0q, g_W0);

    // Stage bytes: A (128*80) + B (BN*80); 4 buffers.
    constexpr int SM128 = 4 * (128 * 80 + 128 * 80);   // 81920 -> 2 CTAs/SM
    constexpr int SM64  = 4 * (128 * 80 + 64 * 80);    // 61440
    cudaFuncSetAttribute(hnn_mma<0, 128, 4>, cudaFuncAttributeMaxDynamicSharedMemorySize, SM128);
    cudaFuncSetAttribute(hnn_mma<1, 128, 4>, cudaFuncAttributeMaxDynamicSharedMemorySize, SM128);
    cudaFuncSetAttribute(hnn_mma<2, 128, 4>, cudaFuncAttributeMaxDynamicSharedMemorySize, SM128);
    cudaFuncSetAttribute(hnn_mma<3, 64, 8>,  cudaFuncAttributeMaxDynamicSharedMemorySize, SM64);

    // ---- prep: 2 launches (x convert; all weights fused) ----
    {
        int n = BB * DD;
        half_direct<<<(n + 255) / 256, 256>>>(x, xq, n);
        int nw = NW0 + 2 * NWH;                      // 557056
        prep_weights<<<(nw + 255) / 256, 256>>>(W0, W1, W2,
                                                W0q, W0T, W1q, W1T, W2q, W2T);
    }

    const dim3 gH(HH / 128, BB / 128);   // (4, 512)
    const dim3 gO(1,        BB / 128);   // (1, 512)

    // 1) h0 = tanh(x @ W0 + b0)
    hnn_mma<0, 128, 4><<<gH, 256, SM128>>>(xq, W0T, b0, nullptr, nullptr, h0, nullptr, DD);
    // 2) h1 = tanh(h0 @ W1 + b1)
    hnn_mma<0, 128, 4><<<gH, 256, SM128>>>(h0, W1T, b1, nullptr, nullptr, h1, nullptr, HH);
    // 3) d2 = W3 * (1 - tanh^2(h1 @ W2 + b2))
    hnn_mma<1, 128, 4><<<gH, 256, SM128>>>(h1, W2T, b2, W3, nullptr, da, nullptr, HH);
    // 4) d1 = (d2 @ W2^T) * (1 - h1^2)
    hnn_mma<2, 128, 4><<<gH, 256, SM128>>>(da, W2q, nullptr, nullptr, h1, d1, nullptr, HH);
    // 5) d0 = (d1 @ W1^T) * (1 - h0^2)   (reuse da buffer)
    hnn_mma<2, 128, 4><<<gH, 256, SM128>>>(d1, W1q, nullptr, nullptr, h0, da, nullptr, HH);
    // 6) out = symplectic(d0 @ W0^T)
    hnn_mma<3, 64, 8><<<gO, 256, SM64>>>(da, W0q, nullptr, nullptr, nullptr, nullptr, out, HH);
}